// round 5
// baseline (speedup 1.0000x reference)
#include <cuda_runtime.h>
#include <float.h>

// Fused: out[b,c,y,x] = relu( p1[b,c%128,y,x] + p2[b,c%64,y,x]
//                           + p3[b,c%32,y,x] + p4[b,c%16,y,x] + ff[b,c,y,x] )
// pk = non-overlapping max-pool of input_tensor_k.
//
// One CTA per (b, y, x-sixth): HX=4 output columns. Every phase is exactly
// 256 work items (1 per thread, no loops, no idle threads):
//   t4: 16c x 4x x 4 row-quarters   (partials combined in assemble)
//   t3: 32c x 4x x 2 row-halves     (partials combined in assemble)
//   t2: 64c x 4x
//   t1: 128c x 2 float4-pairs (2 outputs each)
//   assemble: 256c x 1 float4
// 2304 CTAs x 256 thr, occ 8 -> ~1.95 waves; wave>=2 work-stealing amortizes
// the between-SM L2-die completion spread that capped DRAM at 74%.

#define NB 16
#define HW 24
#define HX 4
#define THREADS 256

__global__ __launch_bounds__(THREADS, 8)
void fused_ffblock_kernel(const float* __restrict__ t1,   // [16,128,48,48]
                          const float* __restrict__ t2,   // [16, 64,96,96]
                          const float* __restrict__ t3,   // [16, 32,192,192]
                          const float* __restrict__ t4,   // [16, 16,384,384]
                          const float* __restrict__ ff,   // [16,256,24,24]
                          float* __restrict__ out)        // [16,256,24,24]
{
    const int bx  = blockIdx.x;
    const int xh  = bx % 6;                  // x-sixth
    const int y   = (bx / 6) % HW;
    const int b   = bx / (6 * HW);
    const int tid = threadIdx.x;
    const int xbase = xh * HX;

    __shared__ __align__(16) float p4part[4 * 16 * HX];   // [q][c][l]  256
    __shared__ __align__(16) float p3part[2 * 32 * HX];   // [h][c][l]  256
    __shared__ __align__(16) float p2s[64 * HX];          // [c][l]     256
    __shared__ __align__(16) float p1s[128 * HX];         // [c][x]     512

    // ---- t4: k=16, 16 ch, input 384x384. item = (q, c, l): 4 rows x 4 float4.
    {
        const int q = tid >> 6;              // row quarter
        const int j = tid & 63;
        const int c = j >> 2, l = j & 3;
        const float* rowp = t4 + ((b * 16 + c) * 384 + y * 16 + q * 4) * 384
                               + (xbase + l) * 16;
        float4 m = make_float4(-FLT_MAX, -FLT_MAX, -FLT_MAX, -FLT_MAX);
        #pragma unroll
        for (int r = 0; r < 4; ++r) {
            const float4* p = reinterpret_cast<const float4*>(rowp + r * 384);
            float4 v0 = p[0], v1 = p[1], v2 = p[2], v3 = p[3];
            m.x = fmaxf(m.x, fmaxf(fmaxf(v0.x, v1.x), fmaxf(v2.x, v3.x)));
            m.y = fmaxf(m.y, fmaxf(fmaxf(v0.y, v1.y), fmaxf(v2.y, v3.y)));
            m.z = fmaxf(m.z, fmaxf(fmaxf(v0.z, v1.z), fmaxf(v2.z, v3.z)));
            m.w = fmaxf(m.w, fmaxf(fmaxf(v0.w, v1.w), fmaxf(v2.w, v3.w)));
        }
        p4part[tid] = fmaxf(fmaxf(m.x, m.y), fmaxf(m.z, m.w));
    }

    // ---- t3: k=8, 32 ch, input 192x192. item = (h, c, l): 4 rows x 2 float4.
    {
        const int h = tid >> 7;              // row half
        const int j = tid & 127;
        const int c = j >> 2, l = j & 3;
        const float* rowp = t3 + ((b * 32 + c) * 192 + y * 8 + h * 4) * 192
                               + (xbase + l) * 8;
        float4 m = make_float4(-FLT_MAX, -FLT_MAX, -FLT_MAX, -FLT_MAX);
        #pragma unroll
        for (int r = 0; r < 4; ++r) {
            const float4* p = reinterpret_cast<const float4*>(rowp + r * 192);
            float4 v0 = p[0], v1 = p[1];
            m.x = fmaxf(m.x, fmaxf(v0.x, v1.x));
            m.y = fmaxf(m.y, fmaxf(v0.y, v1.y));
            m.z = fmaxf(m.z, fmaxf(v0.z, v1.z));
            m.w = fmaxf(m.w, fmaxf(v0.w, v1.w));
        }
        p3part[tid] = fmaxf(fmaxf(m.x, m.y), fmaxf(m.z, m.w));
    }

    // ---- t2: k=4, 64 ch, input 96x96. item = (c, l): 4 rows x 1 float4.
    {
        const int c = tid >> 2, l = tid & 3;
        const float* rowp = t2 + ((b * 64 + c) * 96 + y * 4) * 96 + (xbase + l) * 4;
        float4 m = make_float4(-FLT_MAX, -FLT_MAX, -FLT_MAX, -FLT_MAX);
        #pragma unroll
        for (int r = 0; r < 4; ++r) {
            float4 v = *reinterpret_cast<const float4*>(rowp + r * 96);
            m.x = fmaxf(m.x, v.x); m.y = fmaxf(m.y, v.y);
            m.z = fmaxf(m.z, v.z); m.w = fmaxf(m.w, v.w);
        }
        p2s[tid] = fmaxf(fmaxf(m.x, m.y), fmaxf(m.z, m.w));
    }

    // ---- t1: k=2, 128 ch, input 48x48. item = (c, xp): one float4 pair -> 2 outputs.
    {
        const int c = tid >> 1, xp = tid & 1;
        const float* rowp = t1 + ((b * 128 + c) * 48 + y * 2) * 48
                               + xbase * 2 + xp * 4;
        float4 v0 = *reinterpret_cast<const float4*>(rowp);
        float4 v1 = *reinterpret_cast<const float4*>(rowp + 48);
        p1s[c * HX + xp * 2 + 0] = fmaxf(fmaxf(v0.x, v0.y), fmaxf(v1.x, v1.y));
        p1s[c * HX + xp * 2 + 1] = fmaxf(fmaxf(v0.z, v0.w), fmaxf(v1.z, v1.w));
    }

    __syncthreads();

    // ---- assemble: one float4 per thread (c = tid, x = xbase..xbase+3).
    {
        const int c  = tid;
        const int c1 = c & 127, c2 = c & 63, c3 = c & 31, c4 = c & 15;
        const int g  = ((b * 256 + c) * HW + y) * HW + xbase;

        float4 f  = *reinterpret_cast<const float4*>(ff + g);
        float4 a1 = *reinterpret_cast<const float4*>(&p1s[c1 * HX]);
        float4 a2 = *reinterpret_cast<const float4*>(&p2s[c2 * HX]);

        float4 b0 = *reinterpret_cast<const float4*>(&p3part[c3 * HX]);
        float4 b1 = *reinterpret_cast<const float4*>(&p3part[128 + c3 * HX]);
        float4 a3;
        a3.x = fmaxf(b0.x, b1.x); a3.y = fmaxf(b0.y, b1.y);
        a3.z = fmaxf(b0.z, b1.z); a3.w = fmaxf(b0.w, b1.w);

        float4 q0 = *reinterpret_cast<const float4*>(&p4part[c4 * HX]);
        float4 q1 = *reinterpret_cast<const float4*>(&p4part[64 + c4 * HX]);
        float4 q2 = *reinterpret_cast<const float4*>(&p4part[128 + c4 * HX]);
        float4 q3 = *reinterpret_cast<const float4*>(&p4part[192 + c4 * HX]);
        float4 a4;
        a4.x = fmaxf(fmaxf(q0.x, q1.x), fmaxf(q2.x, q3.x));
        a4.y = fmaxf(fmaxf(q0.y, q1.y), fmaxf(q2.y, q3.y));
        a4.z = fmaxf(fmaxf(q0.z, q1.z), fmaxf(q2.z, q3.z));
        a4.w = fmaxf(fmaxf(q0.w, q1.w), fmaxf(q2.w, q3.w));

        float4 r;
        r.x = fmaxf(f.x + a1.x + a2.x + a3.x + a4.x, 0.f);
        r.y = fmaxf(f.y + a1.y + a2.y + a3.y + a4.y, 0.f);
        r.z = fmaxf(f.z + a1.z + a2.z + a3.z + a4.z, 0.f);
        r.w = fmaxf(f.w + a1.w + a2.w + a3.w + a4.w, 0.f);

        *reinterpret_cast<float4*>(out + g) = r;
    }
}

extern "C" void kernel_launch(void* const* d_in, const int* in_sizes, int n_in,
                              void* d_out, int out_size) {
    const float* t1 = (const float*)d_in[0];
    const float* t2 = (const float*)d_in[1];
    const float* t3 = (const float*)d_in[2];
    const float* t4 = (const float*)d_in[3];
    const float* ff = (const float*)d_in[4];
    float* out = (float*)d_out;

    dim3 grid(NB * HW * 6);   // 2304 CTAs: one per (batch, row, x-sixth)
    dim3 block(THREADS);
    fused_ffblock_kernel<<<grid, block>>>(t1, t2, t3, t4, ff, out);
}

// round 6
// speedup vs baseline: 1.1093x; 1.1093x over previous
#include <cuda_runtime.h>
#include <float.h>

// Fused: out[b,c,y,x] = relu( p1[b,c%128,y,x] + p2[b,c%64,y,x]
//                           + p3[b,c%32,y,x] + p4[b,c%16,y,x] + ff[b,c,y,x] )
// pk = non-overlapping max-pool of input_tensor_k.
//
// One CTA per (b, y, x-third), HX=8. KEY CHANGE vs earlier rounds: every
// pooling LDG.128 is warp-coalesced — 32 lanes read 512B CONTIGUOUS and
// line-aligned (nL=4 wavefronts, the minimum), with window maxima formed by
// __shfl_xor lane reductions instead of window-strided addressing. This
// collapses the L1tex wavefront count (~3.5x) that was capping DRAM at 74%.
// 1152 CTAs x 256 threads, occ 8, single wave.

#define HW 24
#define HX 8
#define THREADS 256
#define FULL 0xFFFFFFFFu

__device__ __forceinline__ float hmax4(float4 v) {
    return fmaxf(fmaxf(v.x, v.y), fmaxf(v.z, v.w));
}

__global__ __launch_bounds__(THREADS, 8)
void fused_ffblock_kernel(const float* __restrict__ t1,   // [16,128,48,48]
                          const float* __restrict__ t2,   // [16, 64,96,96]
                          const float* __restrict__ t3,   // [16, 32,192,192]
                          const float* __restrict__ t4,   // [16, 16,384,384]
                          const float* __restrict__ ff,   // [16,256,24,24]
                          float* __restrict__ out)        // [16,256,24,24]
{
    const int bx   = blockIdx.x;
    const int xh   = bx % 3;
    const int y    = (bx / 3) % HW;
    const int b    = bx / (3 * HW);
    const int tid  = threadIdx.x;
    const int w    = tid >> 5;
    const int lane = tid & 31;
    const int xbase = xh * HX;

    __shared__ __align__(16) float p4s[16 * HX];
    __shared__ __align__(16) float p3s[32 * HX];
    __shared__ __align__(16) float p2s[64 * HX];
    __shared__ __align__(16) float p1s[128 * HX];

    // ---- t4: k=16, 16 ch. Warp handles c = w, w+8. Each LDG: 512B contiguous
    // (one window-row: 8 windows x 16 floats), 16 rows accumulated.
    #pragma unroll
    for (int ci = 0; ci < 2; ++ci) {
        const int c = w + ci * 8;
        const float* base = t4 + (((b * 16 + c) * 384 + y * 16) * 384)
                               + xbase * 16 + lane * 4;
        float4 m = make_float4(-FLT_MAX, -FLT_MAX, -FLT_MAX, -FLT_MAX);
        #pragma unroll 4
        for (int r = 0; r < 16; ++r) {
            float4 v = *reinterpret_cast<const float4*>(base + r * 384);
            m.x = fmaxf(m.x, v.x); m.y = fmaxf(m.y, v.y);
            m.z = fmaxf(m.z, v.z); m.w = fmaxf(m.w, v.w);
        }
        float s = hmax4(m);                       // max of this lane's 16B slot
        s = fmaxf(s, __shfl_xor_sync(FULL, s, 1)); // window = 4 lanes (64B)
        s = fmaxf(s, __shfl_xor_sync(FULL, s, 2));
        if ((lane & 3) == 0) p4s[c * HX + (lane >> 2)] = s;
    }

    // ---- t3: k=8, 32 ch. Warp handles c = w, w+8, w+16, w+24. Each LDG:
    // lanes 0-15 = row 2i (256B, 2 lines), lanes 16-31 = row 2i+1.
    #pragma unroll
    for (int ci = 0; ci < 4; ++ci) {
        const int c  = w + ci * 8;
        const int rp = lane >> 4;                 // row parity
        const int sl = lane & 15;                 // 16B slot within 256B row-chunk
        const float* base = t3 + (((b * 32 + c) * 192 + y * 8 + rp) * 192)
                               + xbase * 8 + sl * 4;
        float4 m = make_float4(-FLT_MAX, -FLT_MAX, -FLT_MAX, -FLT_MAX);
        #pragma unroll
        for (int i = 0; i < 4; ++i) {             // rows 2i+rp
            float4 v = *reinterpret_cast<const float4*>(base + i * 384);
            m.x = fmaxf(m.x, v.x); m.y = fmaxf(m.y, v.y);
            m.z = fmaxf(m.z, v.z); m.w = fmaxf(m.w, v.w);
        }
        float s = hmax4(m);
        s = fmaxf(s, __shfl_xor_sync(FULL, s, 1));  // window = 2 slots (32B)
        s = fmaxf(s, __shfl_xor_sync(FULL, s, 16)); // combine row parities
        if (lane < 16 && (lane & 1) == 0) p3s[c * HX + (sl >> 1)] = s;
    }

    // ---- t2: k=4, 64 ch. Warp handles c = w*8 .. w*8+7. One LDG per c:
    // 4 rows x 128B line-aligned chunks (nL=4). Lane float4 = one window.
    #pragma unroll
    for (int ci = 0; ci < 8; ++ci) {
        const int c   = w * 8 + ci;
        const int row = lane >> 3;
        const int sl  = lane & 7;                 // window index
        const float* p = t2 + (((b * 64 + c) * 96 + y * 4 + row) * 96)
                            + xbase * 4 + sl * 4;
        float4 v = *reinterpret_cast<const float4*>(p);
        float s = hmax4(v);
        s = fmaxf(s, __shfl_xor_sync(FULL, s, 8));  // combine 4 rows
        s = fmaxf(s, __shfl_xor_sync(FULL, s, 16));
        if (lane < 8) p2s[c * HX + lane] = s;
    }

    // ---- t1: k=2, 128 ch. Warp handles 16 ch as 4 LDGs of (4 ch x 2 rows x 64B).
    // Lane float4 = 2 adjacent windows of one row.
    #pragma unroll
    for (int ci = 0; ci < 4; ++ci) {
        const int c   = w * 16 + ci * 4 + (lane >> 3);
        const int row = (lane >> 2) & 1;
        const int sl  = lane & 3;
        const float* p = t1 + (((b * 128 + c) * 48 + y * 2 + row) * 48)
                            + xbase * 2 + sl * 4;
        float4 v = *reinterpret_cast<const float4*>(p);
        float o0 = fmaxf(v.x, v.y);
        float o1 = fmaxf(v.z, v.w);
        o0 = fmaxf(o0, __shfl_xor_sync(FULL, o0, 4));   // combine 2 rows
        o1 = fmaxf(o1, __shfl_xor_sync(FULL, o1, 4));
        if (((lane >> 2) & 1) == 0) {
            p1s[c * HX + sl * 2 + 0] = o0;
            p1s[c * HX + sl * 2 + 1] = o1;
        }
    }

    __syncthreads();

    // ---- assemble: 256 ch x 8 x = 512 float4 items (2 per thread).
    const int row_base = ((b * 256) * HW + y) * HW + xbase;
    #pragma unroll
    for (int j = tid; j < 256 * (HX / 4); j += THREADS) {
        const int c  = j >> 1;
        const int x0 = (j & 1) * 4;
        const int c1 = c & 127, c2 = c & 63, c3 = c & 31, c4 = c & 15;
        const int g  = row_base + c * (HW * HW) + x0;

        float4 f  = *reinterpret_cast<const float4*>(ff + g);
        float4 a1 = *reinterpret_cast<const float4*>(&p1s[c1 * HX + x0]);
        float4 a2 = *reinterpret_cast<const float4*>(&p2s[c2 * HX + x0]);
        float4 a3 = *reinterpret_cast<const float4*>(&p3s[c3 * HX + x0]);
        float4 a4 = *reinterpret_cast<const float4*>(&p4s[c4 * HX + x0]);

        float4 r;
        r.x = fmaxf(f.x + a1.x + a2.x + a3.x + a4.x, 0.f);
        r.y = fmaxf(f.y + a1.y + a2.y + a3.y + a4.y, 0.f);
        r.z = fmaxf(f.z + a1.z + a2.z + a3.z + a4.z, 0.f);
        r.w = fmaxf(f.w + a1.w + a2.w + a3.w + a4.w, 0.f);

        *reinterpret_cast<float4*>(out + g) = r;
    }
}

extern "C" void kernel_launch(void* const* d_in, const int* in_sizes, int n_in,
                              void* d_out, int out_size) {
    const float* t1 = (const float*)d_in[0];
    const float* t2 = (const float*)d_in[1];
    const float* t3 = (const float*)d_in[2];
    const float* t4 = (const float*)d_in[3];
    const float* ff = (const float*)d_in[4];
    float* out = (float*)d_out;

    dim3 grid(16 * HW * 3);   // 1152 CTAs: one per (batch, row, x-third)
    dim3 block(THREADS);
    fused_ffblock_kernel<<<grid, block>>>(t1, t2, t3, t4, ff, out);
}

// round 7
// speedup vs baseline: 1.1591x; 1.0449x over previous
#include <cuda_runtime.h>
#include <float.h>

// Fused: out[b,c,y,x] = relu( p1[b,c%128,y,x] + p2[b,c%64,y,x]
//                           + p3[b,c%32,y,x] + p4[b,c%16,y,x] + ff[b,c,y,x] )
// pk = non-overlapping max-pool of input_tensor_k.
//
// R6 structure (warp-coalesced nL=4 LDG.128 + shfl_xor window reductions,
// one CTA per (b, y, x-third), HX=8) plus:
//  - __ldcs / __stcs streaming hints: all data is touched exactly once, so
//    evict-first keeps the 302MB stream from occupying L2 sets.
//  - occ 4 (1152 CTAs -> 1.95 waves): wave>=2 work-stealing amortizes the
//    ~1.10 between-SM completion-spread floor a single wave pays in full.

#define HW 24
#define HX 8
#define THREADS 256
#define FULL 0xFFFFFFFFu

__device__ __forceinline__ float hmax4(float4 v) {
    return fmaxf(fmaxf(v.x, v.y), fmaxf(v.z, v.w));
}

__device__ __forceinline__ float4 ldcs4(const float* p) {
    return __ldcs(reinterpret_cast<const float4*>(p));
}

__global__ __launch_bounds__(THREADS, 4)
void fused_ffblock_kernel(const float* __restrict__ t1,   // [16,128,48,48]
                          const float* __restrict__ t2,   // [16, 64,96,96]
                          const float* __restrict__ t3,   // [16, 32,192,192]
                          const float* __restrict__ t4,   // [16, 16,384,384]
                          const float* __restrict__ ff,   // [16,256,24,24]
                          float* __restrict__ out)        // [16,256,24,24]
{
    const int bx   = blockIdx.x;
    const int xh   = bx % 3;
    const int y    = (bx / 3) % HW;
    const int b    = bx / (3 * HW);
    const int tid  = threadIdx.x;
    const int w    = tid >> 5;
    const int lane = tid & 31;
    const int xbase = xh * HX;

    __shared__ __align__(16) float p4s[16 * HX];
    __shared__ __align__(16) float p3s[32 * HX];
    __shared__ __align__(16) float p2s[64 * HX];
    __shared__ __align__(16) float p1s[128 * HX];

    // ---- t4: k=16, 16 ch. Warp handles c = w, w+8. Each LDG: 512B contiguous
    // (one window-row: 8 windows x 16 floats), 16 rows accumulated.
    #pragma unroll
    for (int ci = 0; ci < 2; ++ci) {
        const int c = w + ci * 8;
        const float* base = t4 + (((b * 16 + c) * 384 + y * 16) * 384)
                               + xbase * 16 + lane * 4;
        float4 m = make_float4(-FLT_MAX, -FLT_MAX, -FLT_MAX, -FLT_MAX);
        #pragma unroll 4
        for (int r = 0; r < 16; ++r) {
            float4 v = ldcs4(base + r * 384);
            m.x = fmaxf(m.x, v.x); m.y = fmaxf(m.y, v.y);
            m.z = fmaxf(m.z, v.z); m.w = fmaxf(m.w, v.w);
        }
        float s = hmax4(m);                        // this lane's 16B slot
        s = fmaxf(s, __shfl_xor_sync(FULL, s, 1)); // window = 4 lanes (64B)
        s = fmaxf(s, __shfl_xor_sync(FULL, s, 2));
        if ((lane & 3) == 0) p4s[c * HX + (lane >> 2)] = s;
    }

    // ---- t3: k=8, 32 ch. Warp handles c = w, w+8, w+16, w+24. Each LDG:
    // lanes 0-15 = row 2i (256B), lanes 16-31 = row 2i+1.
    #pragma unroll
    for (int ci = 0; ci < 4; ++ci) {
        const int c  = w + ci * 8;
        const int rp = lane >> 4;                 // row parity
        const int sl = lane & 15;                 // 16B slot within 256B chunk
        const float* base = t3 + (((b * 32 + c) * 192 + y * 8 + rp) * 192)
                               + xbase * 8 + sl * 4;
        float4 m = make_float4(-FLT_MAX, -FLT_MAX, -FLT_MAX, -FLT_MAX);
        #pragma unroll
        for (int i = 0; i < 4; ++i) {             // rows 2i+rp
            float4 v = ldcs4(base + i * 384);
            m.x = fmaxf(m.x, v.x); m.y = fmaxf(m.y, v.y);
            m.z = fmaxf(m.z, v.z); m.w = fmaxf(m.w, v.w);
        }
        float s = hmax4(m);
        s = fmaxf(s, __shfl_xor_sync(FULL, s, 1));  // window = 2 slots (32B)
        s = fmaxf(s, __shfl_xor_sync(FULL, s, 16)); // combine row parities
        if (lane < 16 && (lane & 1) == 0) p3s[c * HX + (sl >> 1)] = s;
    }

    // ---- t2: k=4, 64 ch. Warp handles c = w*8 .. w*8+7. One LDG per c:
    // 4 rows x 128B line-aligned chunks. Lane float4 = one window.
    #pragma unroll
    for (int ci = 0; ci < 8; ++ci) {
        const int c   = w * 8 + ci;
        const int row = lane >> 3;
        const int sl  = lane & 7;                 // window index
        const float* p = t2 + (((b * 64 + c) * 96 + y * 4 + row) * 96)
                            + xbase * 4 + sl * 4;
        float4 v = ldcs4(p);
        float s = hmax4(v);
        s = fmaxf(s, __shfl_xor_sync(FULL, s, 8));  // combine 4 rows
        s = fmaxf(s, __shfl_xor_sync(FULL, s, 16));
        if (lane < 8) p2s[c * HX + lane] = s;
    }

    // ---- t1: k=2, 128 ch. Warp handles 16 ch as 4 LDGs of (4 ch x 2 rows x 64B).
    // Lane float4 = 2 adjacent windows of one row.
    #pragma unroll
    for (int ci = 0; ci < 4; ++ci) {
        const int c   = w * 16 + ci * 4 + (lane >> 3);
        const int row = (lane >> 2) & 1;
        const int sl  = lane & 3;
        const float* p = t1 + (((b * 128 + c) * 48 + y * 2 + row) * 48)
                            + xbase * 2 + sl * 4;
        float4 v = ldcs4(p);
        float o0 = fmaxf(v.x, v.y);
        float o1 = fmaxf(v.z, v.w);
        o0 = fmaxf(o0, __shfl_xor_sync(FULL, o0, 4));   // combine 2 rows
        o1 = fmaxf(o1, __shfl_xor_sync(FULL, o1, 4));
        if (((lane >> 2) & 1) == 0) {
            p1s[c * HX + sl * 2 + 0] = o0;
            p1s[c * HX + sl * 2 + 1] = o1;
        }
    }

    __syncthreads();

    // ---- assemble: 256 ch x 8 x = 512 float4 items (2 per thread).
    const int row_base = ((b * 256) * HW + y) * HW + xbase;
    #pragma unroll
    for (int j = tid; j < 256 * (HX / 4); j += THREADS) {
        const int c  = j >> 1;
        const int x0 = (j & 1) * 4;
        const int c1 = c & 127, c2 = c & 63, c3 = c & 31, c4 = c & 15;
        const int g  = row_base + c * (HW * HW) + x0;

        float4 f  = __ldcs(reinterpret_cast<const float4*>(ff + g));
        float4 a1 = *reinterpret_cast<const float4*>(&p1s[c1 * HX + x0]);
        float4 a2 = *reinterpret_cast<const float4*>(&p2s[c2 * HX + x0]);
        float4 a3 = *reinterpret_cast<const float4*>(&p3s[c3 * HX + x0]);
        float4 a4 = *reinterpret_cast<const float4*>(&p4s[c4 * HX + x0]);

        float4 r;
        r.x = fmaxf(f.x + a1.x + a2.x + a3.x + a4.x, 0.f);
        r.y = fmaxf(f.y + a1.y + a2.y + a3.y + a4.y, 0.f);
        r.z = fmaxf(f.z + a1.z + a2.z + a3.z + a4.z, 0.f);
        r.w = fmaxf(f.w + a1.w + a2.w + a3.w + a4.w, 0.f);

        __stcs(reinterpret_cast<float4*>(out + g), r);
    }
}

extern "C" void kernel_launch(void* const* d_in, const int* in_sizes, int n_in,
                              void* d_out, int out_size) {
    const float* t1 = (const float*)d_in[0];
    const float* t2 = (const float*)d_in[1];
    const float* t3 = (const float*)d_in[2];
    const float* t4 = (const float*)d_in[3];
    const float* ff = (const float*)d_in[4];
    float* out = (float*)d_out;

    dim3 grid(16 * HW * 3);   // 1152 CTAs; occ 4 -> ~1.95 waves (work-stealing)
    dim3 block(THREADS);
    fused_ffblock_kernel<<<grid, block>>>(t1, t2, t3, t4, ff, out);
}